// round 6
// baseline (speedup 1.0000x reference)
#include <cuda_runtime.h>
#include <cuda_fp16.h>
#include <cstdint>

#define N_NODES_MAX 100000
#define DIM     64
#define MAX_SCAN_BLOCKS 256

// ---- scratch (allocation-free rule: __device__ globals) ----
__device__ __align__(256) __half g_h16[N_NODES_MAX * DIM];  // fp16 feature*norm_src
__device__ __align__(256) float g_accum[N_NODES_MAX * DIM]; // segment_sum * norm_dst
__device__ int g_count[N_NODES_MAX];         // per-dst degree
__device__ int g_offset[N_NODES_MAX];        // exclusive scan (PARTIAL per 1024-tile)
__device__ int g_sorted_src[2000000];        // src indices grouped by dst
__device__ int g_blocksums[MAX_SCAN_BLOCKS]; // scanned tile sums
__device__ int g_scan_ctr = 0;               // ticket; reset by last block each run

// ---------------------------------------------------------------------------
// K1: h16 = fp16(feature * norm) ; histogram of dst (g_count pre-zeroed)
// ---------------------------------------------------------------------------
__global__ void prep_hist_kernel(const float* __restrict__ feature,
                                 const float* __restrict__ norm,
                                 const int* __restrict__ dst,
                                 int n_vec4, int e) {
    int idx = blockIdx.x * blockDim.x + threadIdx.x;
    if (idx < n_vec4) {
        int node = idx >> 4;
        float nv = __ldg(norm + node);
        float4 f = reinterpret_cast<const float4*>(feature)[idx];
        __half2 lo = __floats2half2_rn(f.x * nv, f.y * nv);
        __half2 hi = __floats2half2_rn(f.z * nv, f.w * nv);
        uint2 pack;
        pack.x = *reinterpret_cast<uint32_t*>(&lo);
        pack.y = *reinterpret_cast<uint32_t*>(&hi);
        reinterpret_cast<uint2*>(g_h16)[idx] = pack;
    }
    if (idx < e) atomicAdd(&g_count[__ldg(dst + idx)], 1);
}

// ---------------------------------------------------------------------------
// K2: single-pass scan. Per-1024-tile exclusive scan -> g_offset (partial),
// tile totals -> g_blocksums; the LAST block to finish scans g_blocksums.
// g_scan_ctr self-resets so graph replays are deterministic.
// ---------------------------------------------------------------------------
__global__ void scan_kernel(int n, int nb) {
    __shared__ int sh[1024];
    __shared__ int sh2[MAX_SCAN_BLOCKS];
    __shared__ int is_last;
    int tid = threadIdx.x;
    int gid = blockIdx.x * 1024 + tid;
    int v = (gid < n) ? g_count[gid] : 0;
    sh[tid] = v;
    __syncthreads();
#pragma unroll
    for (int d = 1; d < 1024; d <<= 1) {
        int t = (tid >= d) ? sh[tid - d] : 0;
        __syncthreads();
        sh[tid] += t;
        __syncthreads();
    }
    if (gid < n) g_offset[gid] = sh[tid] - v;   // exclusive partial
    if (tid == 1023) g_blocksums[blockIdx.x] = sh[1023];

    // ---- last-block finalize: exclusive scan of tile sums ----
    __threadfence();
    if (tid == 0) is_last = (atomicAdd(&g_scan_ctr, 1) == gridDim.x - 1);
    __syncthreads();
    if (!is_last) return;
    __threadfence();
    int w = 0;
    if (tid < MAX_SCAN_BLOCKS) {
        w = (tid < nb) ? g_blocksums[tid] : 0;
        sh2[tid] = w;
    }
    __syncthreads();
#pragma unroll
    for (int d = 1; d < MAX_SCAN_BLOCKS; d <<= 1) {
        int t = (tid >= d && tid < MAX_SCAN_BLOCKS) ? sh2[tid - d] : 0;
        __syncthreads();
        if (tid < MAX_SCAN_BLOCKS) sh2[tid] += t;
        __syncthreads();
    }
    if (tid < nb) g_blocksums[tid] = sh2[tid] - w;  // exclusive
    if (tid == 0) g_scan_ctr = 0;                    // reset for next replay
}

// ---------------------------------------------------------------------------
// K3: bucket fill. Position = atomicAdd on PARTIAL offset + scanned blocksum.
// ---------------------------------------------------------------------------
__global__ void fill_kernel(const int* __restrict__ src,
                            const int* __restrict__ dst, int e) {
    int i = blockIdx.x * blockDim.x + threadIdx.x;
    if (i >= e) return;
    int d = __ldg(dst + i);
    int old = atomicAdd(&g_offset[d], 1);
    int pos = old + __ldg(g_blocksums + (d >> 10));
    g_sorted_src[pos] = __ldg(src + i);
}

// ---------------------------------------------------------------------------
// K4: gather-accumulate, fp16 rows. ONE WARP PER DST NODE, TWO EDGES PER
// WARP-LDG (lanes 0-15 even edge, 16-31 odd edge). Unroll 16 edges: 8 indices
// prefetched, 8 independent LDG.64 in flight.
// ---------------------------------------------------------------------------
__device__ __forceinline__ void acc_h16(float4& a, uint2 v) {
    float2 lo = __half22float2(*reinterpret_cast<__half2*>(&v.x));
    float2 hi = __half22float2(*reinterpret_cast<__half2*>(&v.y));
    a.x += lo.x; a.y += lo.y; a.z += hi.x; a.w += hi.y;
}

__global__ void __launch_bounds__(256)
gather_kernel(const float* __restrict__ norm, int n) {
    int node = blockIdx.x * 8 + (threadIdx.x >> 5);
    int lane = threadIdx.x & 31;
    if (node >= n) return;
    int half = lane >> 4;     // which edge of the pair
    int c16  = lane & 15;     // 8-byte chunk within the 128 B row

    int deg = __ldg(g_count + node);
    int end = __ldg(g_offset + node) + __ldg(g_blocksums + (node >> 10));
    int k   = end - deg;

    const uint2* __restrict__ h2 = reinterpret_cast<const uint2*>(g_h16);

    float4 acc0 = make_float4(0.f, 0.f, 0.f, 0.f);
    float4 acc1 = make_float4(0.f, 0.f, 0.f, 0.f);
    float4 acc2 = make_float4(0.f, 0.f, 0.f, 0.f);
    float4 acc3 = make_float4(0.f, 0.f, 0.f, 0.f);

    // 16 edges (8 pairs) per iteration: 8 independent data loads in flight
    for (; k + 16 <= end; k += 16) {
        int s[8];
#pragma unroll
        for (int j = 0; j < 8; j++)
            s[j] = __ldg(g_sorted_src + k + 2 * j + half);
        uint2 v[8];
#pragma unroll
        for (int j = 0; j < 8; j++)
            v[j] = __ldg(h2 + (size_t)s[j] * 16 + c16);
        acc_h16(acc0, v[0]); acc_h16(acc1, v[1]);
        acc_h16(acc2, v[2]); acc_h16(acc3, v[3]);
        acc_h16(acc0, v[4]); acc_h16(acc1, v[5]);
        acc_h16(acc2, v[6]); acc_h16(acc3, v[7]);
    }
    // pairs
    for (; k + 2 <= end; k += 2) {
        int s = __ldg(g_sorted_src + k + half);
        uint2 v = __ldg(h2 + (size_t)s * 16 + c16);
        acc_h16(acc0, v);
    }
    // single leftover edge (half-0 lanes only)
    if (k < end && half == 0) {
        int s = __ldg(g_sorted_src + k);
        uint2 v = __ldg(h2 + (size_t)s * 16 + c16);
        acc_h16(acc0, v);
    }

    acc0.x += acc1.x; acc0.y += acc1.y; acc0.z += acc1.z; acc0.w += acc1.w;
    acc2.x += acc3.x; acc2.y += acc3.y; acc2.z += acc3.z; acc2.w += acc3.w;
    acc0.x += acc2.x; acc0.y += acc2.y; acc0.z += acc2.z; acc0.w += acc2.w;

    acc0.x += __shfl_xor_sync(0xffffffffu, acc0.x, 16);
    acc0.y += __shfl_xor_sync(0xffffffffu, acc0.y, 16);
    acc0.z += __shfl_xor_sync(0xffffffffu, acc0.z, 16);
    acc0.w += __shfl_xor_sync(0xffffffffu, acc0.w, 16);

    if (half == 0) {
        float nv = __ldg(norm + node);
        acc0.x *= nv; acc0.y *= nv; acc0.z *= nv; acc0.w *= nv;
        reinterpret_cast<float4*>(g_accum + (size_t)node * DIM)[c16] = acc0;
    }
}

// ---------------------------------------------------------------------------
// K5: out = g_accum @ W^T + b   (f32x2 packed FMA, W transposed in shared)
// Block = 256 threads = 64 nodes x 4 col-groups of 16.
// ---------------------------------------------------------------------------
__global__ void __launch_bounds__(256)
linear_kernel(const float* __restrict__ W,
              const float* __restrict__ b,
              float* __restrict__ out, int n) {
    __shared__ float Wt[DIM * DIM];
    __shared__ float bs[DIM];
    int tid = threadIdx.x;
    for (int k = tid; k < DIM * DIM; k += 256) {
        int j = k >> 6, i = k & 63;
        Wt[i * DIM + j] = W[k];
    }
    if (tid < DIM) bs[tid] = b[tid];
    __syncthreads();

    int node = blockIdx.x * 64 + (tid >> 2);
    int jg   = (tid & 3) * 16;
    if (node >= n) return;

    unsigned long long a01, a23, a45, a67, a89, aab, acd, aef;
    asm("mov.b64 %0, {%1, %2};" : "=l"(a01) : "f"(bs[jg + 0]), "f"(bs[jg + 1]));
    asm("mov.b64 %0, {%1, %2};" : "=l"(a23) : "f"(bs[jg + 2]), "f"(bs[jg + 3]));
    asm("mov.b64 %0, {%1, %2};" : "=l"(a45) : "f"(bs[jg + 4]), "f"(bs[jg + 5]));
    asm("mov.b64 %0, {%1, %2};" : "=l"(a67) : "f"(bs[jg + 6]), "f"(bs[jg + 7]));
    asm("mov.b64 %0, {%1, %2};" : "=l"(a89) : "f"(bs[jg + 8]), "f"(bs[jg + 9]));
    asm("mov.b64 %0, {%1, %2};" : "=l"(aab) : "f"(bs[jg + 10]), "f"(bs[jg + 11]));
    asm("mov.b64 %0, {%1, %2};" : "=l"(acd) : "f"(bs[jg + 12]), "f"(bs[jg + 13]));
    asm("mov.b64 %0, {%1, %2};" : "=l"(aef) : "f"(bs[jg + 14]), "f"(bs[jg + 15]));

    const float4* arow = reinterpret_cast<const float4*>(g_accum + (size_t)node * DIM);
#pragma unroll
    for (int i4 = 0; i4 < 16; i4++) {
        float4 a = arow[i4];
        const float av[4] = {a.x, a.y, a.z, a.w};
#pragma unroll
        for (int c = 0; c < 4; c++) {
            int i = i4 * 4 + c;
            unsigned long long aa;
            asm("mov.b64 %0, {%1, %1};" : "=l"(aa) : "f"(av[c]));
            const ulonglong2* wp = reinterpret_cast<const ulonglong2*>(&Wt[i * DIM + jg]);
            ulonglong2 w0 = wp[0], w1 = wp[1];
            asm("fma.rn.f32x2 %0, %1, %2, %0;" : "+l"(a01) : "l"(aa), "l"(w0.x));
            asm("fma.rn.f32x2 %0, %1, %2, %0;" : "+l"(a23) : "l"(aa), "l"(w0.y));
            asm("fma.rn.f32x2 %0, %1, %2, %0;" : "+l"(a45) : "l"(aa), "l"(w1.x));
            asm("fma.rn.f32x2 %0, %1, %2, %0;" : "+l"(a67) : "l"(aa), "l"(w1.y));
            const ulonglong2* wq = reinterpret_cast<const ulonglong2*>(&Wt[i * DIM + jg + 8]);
            ulonglong2 w2 = wq[0], w3 = wq[1];
            asm("fma.rn.f32x2 %0, %1, %2, %0;" : "+l"(a89) : "l"(aa), "l"(w2.x));
            asm("fma.rn.f32x2 %0, %1, %2, %0;" : "+l"(aab) : "l"(aa), "l"(w2.y));
            asm("fma.rn.f32x2 %0, %1, %2, %0;" : "+l"(acd) : "l"(aa), "l"(w3.x));
            asm("fma.rn.f32x2 %0, %1, %2, %0;" : "+l"(aef) : "l"(aa), "l"(w3.y));
        }
    }

    float r[16];
    asm("mov.b64 {%0, %1}, %2;" : "=f"(r[0]), "=f"(r[1]) : "l"(a01));
    asm("mov.b64 {%0, %1}, %2;" : "=f"(r[2]), "=f"(r[3]) : "l"(a23));
    asm("mov.b64 {%0, %1}, %2;" : "=f"(r[4]), "=f"(r[5]) : "l"(a45));
    asm("mov.b64 {%0, %1}, %2;" : "=f"(r[6]), "=f"(r[7]) : "l"(a67));
    asm("mov.b64 {%0, %1}, %2;" : "=f"(r[8]), "=f"(r[9]) : "l"(a89));
    asm("mov.b64 {%0, %1}, %2;" : "=f"(r[10]), "=f"(r[11]) : "l"(aab));
    asm("mov.b64 {%0, %1}, %2;" : "=f"(r[12]), "=f"(r[13]) : "l"(acd));
    asm("mov.b64 {%0, %1}, %2;" : "=f"(r[14]), "=f"(r[15]) : "l"(aef));
    float4* op = reinterpret_cast<float4*>(out + (size_t)node * DIM + jg);
#pragma unroll
    for (int q = 0; q < 4; q++)
        op[q] = make_float4(r[q * 4], r[q * 4 + 1], r[q * 4 + 2], r[q * 4 + 3]);
}

// ---------------------------------------------------------------------------
// Launch. Inputs: 0 feature [N,64] f32, 1 norm [N] f32, 2 src [E] i32,
//                 3 dst [E] i32, 4 W [64,64] f32, 5 b [64] f32. out [N,64] f32.
// ---------------------------------------------------------------------------
extern "C" void kernel_launch(void* const* d_in, const int* in_sizes, int n_in,
                              void* d_out, int out_size) {
    const float* feature = (const float*)d_in[0];
    const float* norm    = (const float*)d_in[1];
    const int*   src     = (const int*)d_in[2];
    const int*   dst     = (const int*)d_in[3];
    const float* W       = (const float*)d_in[4];
    const float* b       = (const float*)d_in[5];
    float*       out     = (float*)d_out;

    int n = in_sizes[1];
    int e = in_sizes[2];

    void* count_ptr = nullptr;
    cudaGetSymbolAddress(&count_ptr, g_count);
    cudaMemsetAsync(count_ptr, 0, (size_t)n * sizeof(int));

    int n_vec4 = n * 16;
    int work = max(n_vec4, e);
    prep_hist_kernel<<<(work + 255) / 256, 256>>>(feature, norm, dst, n_vec4, e);

    int nb = (n + 1023) / 1024;
    scan_kernel<<<nb, 1024>>>(n, nb);

    fill_kernel<<<(e + 511) / 512, 512>>>(src, dst, e);

    gather_kernel<<<(n + 7) / 8, 256>>>(norm, n);

    linear_kernel<<<(n + 63) / 64, 256>>>(W, b, out, n);
}

// round 7
// speedup vs baseline: 1.1282x; 1.1282x over previous
#include <cuda_runtime.h>
#include <cuda_fp16.h>
#include <cstdint>

#define N_NODES_MAX 100000
#define DIM     64
#define MAX_SCAN_BLOCKS 256

// ---- scratch (allocation-free rule: __device__ globals) ----
__device__ __align__(256) __half g_y16[N_NODES_MAX * DIM];  // fp16 (feature*norm)@W^T
__device__ int g_count[N_NODES_MAX];         // per-dst degree
__device__ int g_offset[N_NODES_MAX];        // exclusive scan (PARTIAL per 1024-tile)
__device__ int g_sorted_src[2000000];        // src indices grouped by dst
__device__ int g_blocksums[MAX_SCAN_BLOCKS]; // scanned tile sums
__device__ int g_scan_ctr = 0;               // ticket; self-resets each run

// ---------------------------------------------------------------------------
// K1: y16 = fp16((feature * norm) @ W^T)  +  dst histogram (count pre-zeroed).
// Block = 256 threads = 64 nodes x 4 col-groups of 16. W^T staged in shared.
// ---------------------------------------------------------------------------
__global__ void __launch_bounds__(256)
transform_hist_kernel(const float* __restrict__ feature,
                      const float* __restrict__ norm,
                      const int* __restrict__ dst,
                      int n, int e, int total_threads) {
    __shared__ float Wt[DIM * DIM];   // Wt[i*64+j] = W[j*64+i]
    __shared__ float bs_unused;       // (bias applied in gather)
    extern __shared__ float dummy[];
    const float* W = nullptr;         // set below via param trick
    (void)bs_unused; (void)dummy; (void)W;

    // NOTE: W passed through feature-relative trick not possible; use real param.
    // (real signature below)
    ;
}

// real transform kernel (separate to keep signature clean)
__global__ void __launch_bounds__(256)
transform_kernel(const float* __restrict__ feature,
                 const float* __restrict__ norm,
                 const float* __restrict__ W,
                 const int* __restrict__ dst,
                 int n, int e) {
    __shared__ float Wt[DIM * DIM];
    int tid = threadIdx.x;
    for (int k = tid; k < DIM * DIM; k += 256) {
        int j = k >> 6, i = k & 63;
        Wt[i * DIM + j] = W[k];
    }

    // fused histogram: grid-stride over edges
    int gid = blockIdx.x * 256 + tid;
    int stride = gridDim.x * 256;
    for (int i = gid; i < e; i += stride)
        atomicAdd(&g_count[__ldg(dst + i)], 1);

    __syncthreads();

    int node = blockIdx.x * 64 + (tid >> 2);
    int jg   = (tid & 3) * 16;
    if (node >= n) return;

    float nv = __ldg(norm + node);

    unsigned long long a01, a23, a45, a67, a89, aab, acd, aef;
    asm("mov.b64 %0, {%1, %1};" : "=l"(a01) : "f"(0.0f));
    a23 = a01; a45 = a01; a67 = a01; a89 = a01; aab = a01; acd = a01; aef = a01;

    const float4* arow = reinterpret_cast<const float4*>(feature + (size_t)node * DIM);
#pragma unroll
    for (int i4 = 0; i4 < 16; i4++) {
        float4 a = arow[i4];
        a.x *= nv; a.y *= nv; a.z *= nv; a.w *= nv;
        const float av[4] = {a.x, a.y, a.z, a.w};
#pragma unroll
        for (int c = 0; c < 4; c++) {
            int i = i4 * 4 + c;
            unsigned long long aa;
            asm("mov.b64 %0, {%1, %1};" : "=l"(aa) : "f"(av[c]));
            const ulonglong2* wp = reinterpret_cast<const ulonglong2*>(&Wt[i * DIM + jg]);
            ulonglong2 w0 = wp[0], w1 = wp[1];
            asm("fma.rn.f32x2 %0, %1, %2, %0;" : "+l"(a01) : "l"(aa), "l"(w0.x));
            asm("fma.rn.f32x2 %0, %1, %2, %0;" : "+l"(a23) : "l"(aa), "l"(w0.y));
            asm("fma.rn.f32x2 %0, %1, %2, %0;" : "+l"(a45) : "l"(aa), "l"(w1.x));
            asm("fma.rn.f32x2 %0, %1, %2, %0;" : "+l"(a67) : "l"(aa), "l"(w1.y));
            const ulonglong2* wq = reinterpret_cast<const ulonglong2*>(&Wt[i * DIM + jg + 8]);
            ulonglong2 w2 = wq[0], w3 = wq[1];
            asm("fma.rn.f32x2 %0, %1, %2, %0;" : "+l"(a89) : "l"(aa), "l"(w2.x));
            asm("fma.rn.f32x2 %0, %1, %2, %0;" : "+l"(aab) : "l"(aa), "l"(w2.y));
            asm("fma.rn.f32x2 %0, %1, %2, %0;" : "+l"(acd) : "l"(aa), "l"(w3.x));
            asm("fma.rn.f32x2 %0, %1, %2, %0;" : "+l"(aef) : "l"(aa), "l"(w3.y));
        }
    }

    float r[16];
    asm("mov.b64 {%0, %1}, %2;" : "=f"(r[0]), "=f"(r[1]) : "l"(a01));
    asm("mov.b64 {%0, %1}, %2;" : "=f"(r[2]), "=f"(r[3]) : "l"(a23));
    asm("mov.b64 {%0, %1}, %2;" : "=f"(r[4]), "=f"(r[5]) : "l"(a45));
    asm("mov.b64 {%0, %1}, %2;" : "=f"(r[6]), "=f"(r[7]) : "l"(a67));
    asm("mov.b64 {%0, %1}, %2;" : "=f"(r[8]), "=f"(r[9]) : "l"(a89));
    asm("mov.b64 {%0, %1}, %2;" : "=f"(r[10]), "=f"(r[11]) : "l"(aab));
    asm("mov.b64 {%0, %1}, %2;" : "=f"(r[12]), "=f"(r[13]) : "l"(acd));
    asm("mov.b64 {%0, %1}, %2;" : "=f"(r[14]), "=f"(r[15]) : "l"(aef));

    // pack 16 floats -> 8 half2 -> 32 bytes, store as 2x uint4
    uint4 p0, p1;
    __half2 h;
    h = __floats2half2_rn(r[0],  r[1]);  p0.x = *reinterpret_cast<uint32_t*>(&h);
    h = __floats2half2_rn(r[2],  r[3]);  p0.y = *reinterpret_cast<uint32_t*>(&h);
    h = __floats2half2_rn(r[4],  r[5]);  p0.z = *reinterpret_cast<uint32_t*>(&h);
    h = __floats2half2_rn(r[6],  r[7]);  p0.w = *reinterpret_cast<uint32_t*>(&h);
    h = __floats2half2_rn(r[8],  r[9]);  p1.x = *reinterpret_cast<uint32_t*>(&h);
    h = __floats2half2_rn(r[10], r[11]); p1.y = *reinterpret_cast<uint32_t*>(&h);
    h = __floats2half2_rn(r[12], r[13]); p1.z = *reinterpret_cast<uint32_t*>(&h);
    h = __floats2half2_rn(r[14], r[15]); p1.w = *reinterpret_cast<uint32_t*>(&h);
    uint4* yp = reinterpret_cast<uint4*>(g_y16 + (size_t)node * DIM + jg);
    yp[0] = p0;
    yp[1] = p1;
}

// ---------------------------------------------------------------------------
// K2: single-pass scan (last block finalizes tile sums; counter self-resets)
// ---------------------------------------------------------------------------
__global__ void scan_kernel(int n, int nb) {
    __shared__ int sh[1024];
    __shared__ int sh2[MAX_SCAN_BLOCKS];
    __shared__ int is_last;
    int tid = threadIdx.x;
    int gid = blockIdx.x * 1024 + tid;
    int v = (gid < n) ? g_count[gid] : 0;
    sh[tid] = v;
    __syncthreads();
#pragma unroll
    for (int d = 1; d < 1024; d <<= 1) {
        int t = (tid >= d) ? sh[tid - d] : 0;
        __syncthreads();
        sh[tid] += t;
        __syncthreads();
    }
    if (gid < n) g_offset[gid] = sh[tid] - v;
    if (tid == 1023) g_blocksums[blockIdx.x] = sh[1023];

    __threadfence();
    if (tid == 0) is_last = (atomicAdd(&g_scan_ctr, 1) == gridDim.x - 1);
    __syncthreads();
    if (!is_last) return;
    __threadfence();
    int w = 0;
    if (tid < MAX_SCAN_BLOCKS) {
        w = (tid < nb) ? g_blocksums[tid] : 0;
        sh2[tid] = w;
    }
    __syncthreads();
#pragma unroll
    for (int d = 1; d < MAX_SCAN_BLOCKS; d <<= 1) {
        int t = (tid >= d && tid < MAX_SCAN_BLOCKS) ? sh2[tid - d] : 0;
        __syncthreads();
        if (tid < MAX_SCAN_BLOCKS) sh2[tid] += t;
        __syncthreads();
    }
    if (tid < nb) g_blocksums[tid] = sh2[tid] - w;
    if (tid == 0) g_scan_ctr = 0;
}

// ---------------------------------------------------------------------------
// K3: bucket fill
// ---------------------------------------------------------------------------
__global__ void fill_kernel(const int* __restrict__ src,
                            const int* __restrict__ dst, int e) {
    int i = blockIdx.x * blockDim.x + threadIdx.x;
    if (i >= e) return;
    int d = __ldg(dst + i);
    int old = atomicAdd(&g_offset[d], 1);
    int pos = old + __ldg(g_blocksums + (d >> 10));
    g_sorted_src[pos] = __ldg(src + i);
}

// ---------------------------------------------------------------------------
// K4: gather-accumulate + epilogue. ONE WARP PER DST NODE, 2 edges/warp-LDG.
// out[node] = norm[node] * sum(y16[src]) + b.  Unroll-8 main, 4/2/1 tails.
// ---------------------------------------------------------------------------
__device__ __forceinline__ void acc_h16(float4& a, uint2 v) {
    float2 lo = __half22float2(*reinterpret_cast<__half2*>(&v.x));
    float2 hi = __half22float2(*reinterpret_cast<__half2*>(&v.y));
    a.x += lo.x; a.y += lo.y; a.z += hi.x; a.w += hi.y;
}

__global__ void __launch_bounds__(256)
gather_kernel(const float* __restrict__ norm,
              const float* __restrict__ b,
              float* __restrict__ out, int n) {
    int node = blockIdx.x * 8 + (threadIdx.x >> 5);
    int lane = threadIdx.x & 31;
    if (node >= n) return;
    int half = lane >> 4;     // which edge of the pair
    int c16  = lane & 15;     // 8-byte chunk within the 128 B row

    int deg = __ldg(g_count + node);
    int end = __ldg(g_offset + node) + __ldg(g_blocksums + (node >> 10));
    int k   = end - deg;

    const uint2* __restrict__ y2 = reinterpret_cast<const uint2*>(g_y16);

    float4 acc0 = make_float4(0.f, 0.f, 0.f, 0.f);
    float4 acc1 = make_float4(0.f, 0.f, 0.f, 0.f);
    float4 acc2 = make_float4(0.f, 0.f, 0.f, 0.f);
    float4 acc3 = make_float4(0.f, 0.f, 0.f, 0.f);

    // 8 edges (4 pairs) per iteration
    for (; k + 8 <= end; k += 8) {
        int s0 = __ldg(g_sorted_src + k + 0 + half);
        int s1 = __ldg(g_sorted_src + k + 2 + half);
        int s2 = __ldg(g_sorted_src + k + 4 + half);
        int s3 = __ldg(g_sorted_src + k + 6 + half);
        uint2 v0 = __ldg(y2 + (size_t)s0 * 16 + c16);
        uint2 v1 = __ldg(y2 + (size_t)s1 * 16 + c16);
        uint2 v2 = __ldg(y2 + (size_t)s2 * 16 + c16);
        uint2 v3 = __ldg(y2 + (size_t)s3 * 16 + c16);
        acc_h16(acc0, v0);
        acc_h16(acc1, v1);
        acc_h16(acc2, v2);
        acc_h16(acc3, v3);
    }
    // 4-edge tail (2 pairs)
    if (k + 4 <= end) {
        int s0 = __ldg(g_sorted_src + k + 0 + half);
        int s1 = __ldg(g_sorted_src + k + 2 + half);
        uint2 v0 = __ldg(y2 + (size_t)s0 * 16 + c16);
        uint2 v1 = __ldg(y2 + (size_t)s1 * 16 + c16);
        acc_h16(acc0, v0);
        acc_h16(acc1, v1);
        k += 4;
    }
    // pair tail
    if (k + 2 <= end) {
        int s = __ldg(g_sorted_src + k + half);
        uint2 v = __ldg(y2 + (size_t)s * 16 + c16);
        acc_h16(acc2, v);
        k += 2;
    }
    // single leftover edge (half-0 lanes only)
    if (k < end && half == 0) {
        int s = __ldg(g_sorted_src + k);
        uint2 v = __ldg(y2 + (size_t)s * 16 + c16);
        acc_h16(acc3, v);
    }

    acc0.x += acc1.x; acc0.y += acc1.y; acc0.z += acc1.z; acc0.w += acc1.w;
    acc2.x += acc3.x; acc2.y += acc3.y; acc2.z += acc3.z; acc2.w += acc3.w;
    acc0.x += acc2.x; acc0.y += acc2.y; acc0.z += acc2.z; acc0.w += acc2.w;

    acc0.x += __shfl_xor_sync(0xffffffffu, acc0.x, 16);
    acc0.y += __shfl_xor_sync(0xffffffffu, acc0.y, 16);
    acc0.z += __shfl_xor_sync(0xffffffffu, acc0.z, 16);
    acc0.w += __shfl_xor_sync(0xffffffffu, acc0.w, 16);

    if (half == 0) {
        float nv = __ldg(norm + node);
        float4 bv = reinterpret_cast<const float4*>(b)[c16];
        acc0.x = fmaf(acc0.x, nv, bv.x);
        acc0.y = fmaf(acc0.y, nv, bv.y);
        acc0.z = fmaf(acc0.z, nv, bv.z);
        acc0.w = fmaf(acc0.w, nv, bv.w);
        reinterpret_cast<float4*>(out + (size_t)node * DIM)[c16] = acc0;
    }
}

// ---------------------------------------------------------------------------
// Launch. Inputs: 0 feature [N,64] f32, 1 norm [N] f32, 2 src [E] i32,
//                 3 dst [E] i32, 4 W [64,64] f32, 5 b [64] f32. out [N,64] f32.
// ---------------------------------------------------------------------------
extern "C" void kernel_launch(void* const* d_in, const int* in_sizes, int n_in,
                              void* d_out, int out_size) {
    const float* feature = (const float*)d_in[0];
    const float* norm    = (const float*)d_in[1];
    const int*   src     = (const int*)d_in[2];
    const int*   dst     = (const int*)d_in[3];
    const float* W       = (const float*)d_in[4];
    const float* b       = (const float*)d_in[5];
    float*       out     = (float*)d_out;

    int n = in_sizes[1];
    int e = in_sizes[2];

    void* count_ptr = nullptr;
    cudaGetSymbolAddress(&count_ptr, g_count);
    cudaMemsetAsync(count_ptr, 0, (size_t)n * sizeof(int));

    transform_kernel<<<(n + 63) / 64, 256>>>(feature, norm, W, dst, n, e);

    int nb = (n + 1023) / 1024;
    scan_kernel<<<nb, 1024>>>(n, nb);

    fill_kernel<<<(e + 511) / 512, 512>>>(src, dst, e);

    gather_kernel<<<(n + 7) / 8, 256>>>(norm, b, out, n);
}